// round 13
// baseline (speedup 1.0000x reference)
#include <cuda_runtime.h>
#include <cuda_bf16.h>

// Problem: B=512, S=512, I=64, C=4, H=100, O=7
// out = [output (512*7)] ++ [hidden_states (512*512*100)]

#define ULL unsigned long long

// ---------------- scratch (device globals; no runtime allocation) -----------
__device__ float g_xf[512 * 512 * 100];
__device__ float g_xh[512 * 512 * 100];

// ---------------- helpers ---------------------------------------------------
__device__ __forceinline__ ULL fma2(ULL a, ULL b, ULL c) {
    ULL d;
    asm("fma.rn.f32x2 %0, %1, %2, %3;" : "=l"(d) : "l"(a), "l"(b), "l"(c));
    return d;
}
__device__ __forceinline__ float hsum2(ULL a) {
    float lo, hi;
    asm("mov.b64 {%0,%1}, %2;" : "=f"(lo), "=f"(hi) : "l"(a));
    return lo + hi;
}
__device__ __forceinline__ void unpack2(ULL a, float& lo, float& hi) {
    asm("mov.b64 {%0,%1}, %2;" : "=f"(lo), "=f"(hi) : "l"(a));
}
__device__ __forceinline__ ULL dup2(float v) {
    ULL d;
    asm("mov.b64 %0, {%1,%1};" : "=l"(d) : "f"(v));
    return d;
}
__device__ __forceinline__ float sigmoidf_(float v) {
    return __fdividef(1.f, 1.f + __expf(-v));
}
__device__ __forceinline__ float tanhf_(float v) {
    return 1.f - __fdividef(2.f, __expf(2.f * v) + 1.f);
}

// ---------------- K1: pre-GEMM (R12 version: best measured, 244us) -----------
#define PRE_XSF   (64 * 128)               // xs floats
#define PRE_PITCH 68                       // multiple of 4: float4 aligned
#define PRE_UF    (128 * PRE_PITCH)        // union region floats (sht >= ws)
#define PRE_CBF   256
#define PRE_SMEM  ((PRE_XSF + PRE_UF + PRE_CBF) * 4)

__global__ void __launch_bounds__(256, 3)
pre_kernel(const float* __restrict__ x, const float* __restrict__ ctx,
           const float* __restrict__ Wf_w, const float* __restrict__ Wf_b,
           const float* __restrict__ Wh_w, const float* __restrict__ Wh_b)
{
    extern __shared__ float sm[];
    float* xs  = sm;                      // [64][128]  x transposed
    float* ws  = sm + PRE_XSF;            // [64][68]   w transposed  (union lo)
    float* sht = sm + PRE_XSF;            // [128][68]  store staging (union)
    float* cb  = sm + PRE_XSF + PRE_UF;   // [256]      ctx-folded bias

    const int tid = threadIdx.x;
    const int pg = tid & 31;
    const int jg = tid >> 5;
    const size_t pbase = (size_t)blockIdx.x * 128;

    {
        int r = tid;
        float v = 0.f;
        if (r < 200) {
            const float* W = (r < 100) ? (Wf_w + r * 168) : (Wh_w + (r - 100) * 168);
            v = (r < 100) ? Wf_b[r] : Wh_b[r - 100];
            #pragma unroll
            for (int c = 0; c < 4; c++) v += ctx[c] * W[64 + c];
        }
        cb[r] = v;
    }

    for (int idx = tid; idx < 2048; idx += 256) {
        int p = idx >> 4, k4 = (idx & 15) << 2;
        float4 v = *(const float4*)(x + (pbase + p) * 64 + k4);
        xs[(k4 + 0) * 128 + p] = v.x;
        xs[(k4 + 1) * 128 + p] = v.y;
        xs[(k4 + 2) * 128 + p] = v.z;
        xs[(k4 + 3) * 128 + p] = v.w;
    }
    __syncthreads();

    #pragma unroll 1
    for (int pass = 0; pass < 4; pass++) {
        for (int idx = tid; idx < 1024; idx += 256) {
            int row = idx >> 4, k4 = (idx & 15) << 2;
            int rg = pass * 64 + row;
            int rc = (rg < 200) ? rg : 199;
            const float* W = (rc < 100) ? (Wf_w + rc * 168) : (Wh_w + (rc - 100) * 168);
            float4 v = *(const float4*)(W + k4);
            ws[(k4 + 0) * 68 + row] = v.x;
            ws[(k4 + 1) * 68 + row] = v.y;
            ws[(k4 + 2) * 68 + row] = v.z;
            ws[(k4 + 3) * 68 + row] = v.w;
        }
        __syncthreads();

        ULL acc[4][4];
        #pragma unroll
        for (int a = 0; a < 4; a++)
            #pragma unroll
            for (int b = 0; b < 4; b++) acc[a][b] = 0ull;

        #pragma unroll 8
        for (int k = 0; k < 64; k++) {
            float4 xv = *(const float4*)(xs + k * 128 + pg * 4);
            ulonglong2 wa = *(const ulonglong2*)(ws + k * 68 + jg * 8);
            ulonglong2 wb = *(const ulonglong2*)(ws + k * 68 + jg * 8 + 4);
            ULL x0 = dup2(xv.x), x1 = dup2(xv.y), x2 = dup2(xv.z), x3 = dup2(xv.w);
            acc[0][0] = fma2(wa.x, x0, acc[0][0]);
            acc[0][1] = fma2(wa.x, x1, acc[0][1]);
            acc[0][2] = fma2(wa.x, x2, acc[0][2]);
            acc[0][3] = fma2(wa.x, x3, acc[0][3]);
            acc[1][0] = fma2(wa.y, x0, acc[1][0]);
            acc[1][1] = fma2(wa.y, x1, acc[1][1]);
            acc[1][2] = fma2(wa.y, x2, acc[1][2]);
            acc[1][3] = fma2(wa.y, x3, acc[1][3]);
            acc[2][0] = fma2(wb.x, x0, acc[2][0]);
            acc[2][1] = fma2(wb.x, x1, acc[2][1]);
            acc[2][2] = fma2(wb.x, x2, acc[2][2]);
            acc[2][3] = fma2(wb.x, x3, acc[2][3]);
            acc[3][0] = fma2(wb.y, x0, acc[3][0]);
            acc[3][1] = fma2(wb.y, x1, acc[3][1]);
            acc[3][2] = fma2(wb.y, x2, acc[3][2]);
            acc[3][3] = fma2(wb.y, x3, acc[3][3]);
        }
        __syncthreads();  // ws reads done before sht overwrites union

        const int rb = pass * 64 + jg * 8;
        float c0 = cb[rb + 0], c1 = cb[rb + 1], c2 = cb[rb + 2], c3 = cb[rb + 3];
        float c4 = cb[rb + 4], c5 = cb[rb + 5], c6 = cb[rb + 6], c7 = cb[rb + 7];
        #pragma unroll
        for (int i = 0; i < 4; i++) {
            int p = pg * 4 + i;
            float v0, v1, v2, v3, v4, v5, v6, v7;
            unpack2(acc[0][i], v0, v1);
            unpack2(acc[1][i], v2, v3);
            unpack2(acc[2][i], v4, v5);
            unpack2(acc[3][i], v6, v7);
            *(float4*)&sht[p * PRE_PITCH + jg * 8] =
                make_float4(v0 + c0, v1 + c1, v2 + c2, v3 + c3);
            *(float4*)&sht[p * PRE_PITCH + jg * 8 + 4] =
                make_float4(v4 + c4, v5 + c5, v6 + c6, v7 + c7);
        }
        __syncthreads();

        for (int f = tid; f < 2048; f += 256) {
            int pos = f >> 4, r4 = f & 15;
            int rg4 = pass * 64 + r4 * 4;
            float4 v = *(const float4*)&sht[pos * PRE_PITCH + r4 * 4];
            size_t po = (pbase + pos) * 100;
            if (rg4 < 100)       *(float4*)(g_xf + po + rg4)       = v;
            else if (rg4 < 200)  *(float4*)(g_xh + po + rg4 - 100) = v;
        }
        __syncthreads();
    }
}

// ---------------- K2: scan, full-dot per thread, 2 barriers/step -------------
// 128 blocks x 4 batch rows x 400 threads: thread (j = tid>>2, r = tid&3).
// Each thread computes the COMPLETE 100-k dot for (j, r) -> no partials
// exchange, sigmoid/tanh follow the thread's own accumulator; 2 barriers/step
// (vs 4 + exchange in the previous structure).
// Recurrence weights live in SHARED as wsh[gate][j][50 ULL] (row = 100 words
// == 4 mod 32 banks: a warp's 8 j-rows hit 8 disjoint 4-bank groups ->
// conflict-free LDS.128). h rows pitch 116 words -> the 4 r-broadcast
// addresses hit disjoint bank quads.
#define SC_WF   (2 * 100 * 50)            // ULLs of weights (80,000 B)
#define SC_HP   116                        // h row pitch (floats)
#define SC_SMEM (SC_WF * 8 + 2 * 4 * SC_HP * 4)

__global__ void __launch_bounds__(400, 1)
scan_kernel(const float* __restrict__ Wf_w, const float* __restrict__ Wh_w,
            float* __restrict__ hidden)
{
    extern __shared__ __align__(16) unsigned char smraw[];
    ULL*   wsh   = (ULL*)smraw;                       // [2][100][50]
    float* sh_h  = (float*)(wsh + SC_WF);             // [4][116]
    float* sh_fh = sh_h + 4 * SC_HP;                  // [4][116]

    const int tid = threadIdx.x;
    const int j = tid >> 2;     // 0..99
    const int r = tid & 3;      // batch row within block
    const int rbase = blockIdx.x * 4;

    // cooperative weight load: W*_w[j][68 + k] pairs -> wsh[g][j][kp]
    for (int idx = tid; idx < 5000; idx += 400) {
        int g = idx / 2500;
        int rem = idx - g * 2500;
        int jj = rem / 25;
        int kq = rem - jj * 25;            // ulonglong2 index (2 pairs)
        const float* W = g ? Wh_w : Wf_w;
        ulonglong2 v = *(const ulonglong2*)(W + jj * 168 + 68 + 4 * kq);
        ULL* dst = wsh + ((size_t)g * 100 + jj) * 50 + 2 * kq;
        dst[0] = v.x;
        dst[1] = v.y;
    }
    for (int idx = tid; idx < 2 * 4 * SC_HP; idx += 400) sh_h[idx] = 0.f;
    __syncthreads();

    const ULL* wf = wsh + (size_t)j * 50;
    const ULL* wh = wsh + (size_t)(100 + j) * 50;
    const float* hr  = sh_h  + r * SC_HP;
    const float* fhr = sh_fh + r * SC_HP;

    const size_t xbase = (size_t)(rbase + r) * 51200 + j;
    float xf_cur = g_xf[xbase];
    float xh_cur = g_xh[xbase];

    #pragma unroll 1
    for (int s = 0; s < 512; s++) {
        // ---- MV1 + act1: pre_f = wf . h[r] + xf ----------------------------
        ULL a0 = 0ull, a1 = 0ull, a2 = 0ull, a3 = 0ull;
        #pragma unroll
        for (int t = 0; t < 12; t++) {
            ulonglong2 wA = *(const ulonglong2*)&wf[4 * t];
            ulonglong2 wB = *(const ulonglong2*)&wf[4 * t + 2];
            ulonglong2 hA = *(const ulonglong2*)&hr[8 * t];
            ulonglong2 hB = *(const ulonglong2*)&hr[8 * t + 4];
            a0 = fma2(wA.x, hA.x, a0);
            a1 = fma2(wA.y, hA.y, a1);
            a2 = fma2(wB.x, hB.x, a2);
            a3 = fma2(wB.y, hB.y, a3);
        }
        {   // tail: pairs 48,49
            ulonglong2 wA = *(const ulonglong2*)&wf[48];
            ulonglong2 hA = *(const ulonglong2*)&hr[96];
            a0 = fma2(wA.x, hA.x, a0);
            a1 = fma2(wA.y, hA.y, a1);
        }
        float pre_f = hsum2(a0) + hsum2(a1) + hsum2(a2) + hsum2(a3) + xf_cur;
        float fg   = sigmoidf_(pre_f);
        float hold = hr[j];
        sh_fh[r * SC_HP + j] = fg * hold;

        // prefetch next step's pre-activations (overlaps barrier)
        int sp = (s < 511) ? s + 1 : 511;
        float xf_nxt = g_xf[xbase + (size_t)sp * 100];
        float xh_nxt = g_xh[xbase + (size_t)sp * 100];
        __syncthreads();  // (1) sh_fh visible

        // ---- MV2 + act2: pre_h = wh . (f*h)[r] + xh ------------------------
        a0 = a1 = a2 = a3 = 0ull;
        #pragma unroll
        for (int t = 0; t < 12; t++) {
            ulonglong2 wA = *(const ulonglong2*)&wh[4 * t];
            ulonglong2 wB = *(const ulonglong2*)&wh[4 * t + 2];
            ulonglong2 hA = *(const ulonglong2*)&fhr[8 * t];
            ulonglong2 hB = *(const ulonglong2*)&fhr[8 * t + 4];
            a0 = fma2(wA.x, hA.x, a0);
            a1 = fma2(wA.y, hA.y, a1);
            a2 = fma2(wB.x, hB.x, a2);
            a3 = fma2(wB.y, hB.y, a3);
        }
        {   // tail
            ulonglong2 wA = *(const ulonglong2*)&wh[48];
            ulonglong2 hA = *(const ulonglong2*)&fhr[96];
            a0 = fma2(wA.x, hA.x, a0);
            a1 = fma2(wA.y, hA.y, a1);
        }
        float pre_h = hsum2(a0) + hsum2(a1) + hsum2(a2) + hsum2(a3) + xh_cur;
        float ht = tanhf_(pre_h);
        float hn = hold + fg * (ht - hold);
        sh_h[r * SC_HP + j] = hn;
        hidden[((size_t)(rbase + r) * 512 + s) * 100 + j] = hn;
        xf_cur = xf_nxt;
        xh_cur = xh_nxt;
        __syncthreads();  // (2) sh_h visible for next step
    }
}

// ---------------- K3: output head (warp per output) --------------------------
__global__ void head_kernel(const float* __restrict__ hidden,
                            const float* __restrict__ ro_w,
                            const float* __restrict__ ro_b,
                            float* __restrict__ out)
{
    int warp = (blockIdx.x * blockDim.x + threadIdx.x) >> 5;
    int lane = threadIdx.x & 31;
    if (warp >= 512 * 7) return;
    int b = warp / 7, o = warp - b * 7;
    const float* h = hidden + ((size_t)b * 512 + 511) * 100;
    const float* w = ro_w + o * 100;
    float acc = 0.f;
    for (int k = lane; k < 100; k += 32) acc += h[k] * w[k];
    #pragma unroll
    for (int d = 16; d; d >>= 1) acc += __shfl_xor_sync(0xFFFFFFFFu, acc, d);
    if (lane == 0) out[b * 7 + o] = acc + ro_b[o];
}

// ---------------- launch -----------------------------------------------------
extern "C" void kernel_launch(void* const* d_in, const int* in_sizes, int n_in,
                              void* d_out, int out_size)
{
    (void)in_sizes; (void)n_in; (void)out_size;
    const float* x     = (const float*)d_in[0];
    const float* ctx   = (const float*)d_in[1];
    const float* Wf_w  = (const float*)d_in[2];
    const float* Wf_b  = (const float*)d_in[3];
    const float* Wh_w  = (const float*)d_in[4];
    const float* Wh_b  = (const float*)d_in[5];
    const float* ro_w  = (const float*)d_in[6];
    const float* ro_b  = (const float*)d_in[7];

    float* out    = (float*)d_out;
    float* hidden = out + 512 * 7;

    cudaFuncSetAttribute(pre_kernel,
                         cudaFuncAttributeMaxDynamicSharedMemorySize, PRE_SMEM);
    pre_kernel<<<2048, 256, PRE_SMEM>>>(x, ctx, Wf_w, Wf_b, Wh_w, Wh_b);
    cudaFuncSetAttribute(scan_kernel,
                         cudaFuncAttributeMaxDynamicSharedMemorySize, SC_SMEM);
    scan_kernel<<<128, 400, SC_SMEM>>>(Wf_w, Wh_w, hidden);
    head_kernel<<<448, 256>>>(hidden, ro_w, ro_b, out);
}

// round 14
// speedup vs baseline: 1.2984x; 1.2984x over previous
#include <cuda_runtime.h>
#include <cuda_bf16.h>

// Problem: B=512, S=512, I=64, C=4, H=100, O=7
// out = [output (512*7)] ++ [hidden_states (512*512*100)]
//
// Single fused kernel: x-projection GEMM computed per step inside the scan
// (R4 exchange layout, 400 threads — NOT the R7 shfl layout that spilled).
// Deletes the 244us pre-kernel and its 420MB g_xf/g_xh DRAM round-trip.

#define ULL unsigned long long

// ---------------- helpers ---------------------------------------------------
__device__ __forceinline__ ULL fma2(ULL a, ULL b, ULL c) {
    ULL d;
    asm("fma.rn.f32x2 %0, %1, %2, %3;" : "=l"(d) : "l"(a), "l"(b), "l"(c));
    return d;
}
__device__ __forceinline__ float hsum2(ULL a) {
    float lo, hi;
    asm("mov.b64 {%0,%1}, %2;" : "=f"(lo), "=f"(hi) : "l"(a));
    return lo + hi;
}
__device__ __forceinline__ float sigmoidf_(float v) {
    return __fdividef(1.f, 1.f + __expf(-v));
}
__device__ __forceinline__ float tanhf_(float v) {
    return 1.f - __fdividef(2.f, __expf(2.f * v) + 1.f);
}

// ---------------- fused scan -------------------------------------------------
// 128 blocks x 4 batch rows x 400 threads: thread (j = tid%100, c = tid/100).
// h-matvec chunk: k in [28c, 28c+28) (kc=3: 8 real pairs + zero pad).
// x-part   chunk: k in [16c, 16c+16) (8 pairs, exact).
// Partials (h-part + x-part) exchanged via sh_p; activation phase: thread
// (j,c) owns batch row r=c. 4 barriers/step. ctx bias folded per-thread.
// All weights register-resident: 44 ULL = 88 regs (fits 163-reg cap @400thr).
__global__ void __launch_bounds__(400, 1)
scan_fused(const float* __restrict__ x, const float* __restrict__ ctx,
           const float* __restrict__ Wf_w, const float* __restrict__ Wf_b,
           const float* __restrict__ Wh_w, const float* __restrict__ Wh_b,
           float* __restrict__ hidden)
{
    const int tid = threadIdx.x;
    const int c = tid / 100;
    const int j = tid - c * 100;
    const int kb = 28 * c;     // h-chunk base
    const int xk = 16 * c;     // x-chunk base
    const int rbase = blockIdx.x * 4;

    __shared__ __align__(16) float sh_h[4][112];
    __shared__ __align__(16) float sh_fh[4][112];
    __shared__ __align__(16) float sh_p[4][100][4];  // [chunk][j][row]
    __shared__ __align__(16) float xs[2][4][64];     // double-buffered x tiles

    // ---- register-resident weights -----------------------------------------
    ULL wf2[14], wh2[14];      // h-recurrence chunk (pad pairs = 0)
    ULL wfx[8],  whx[8];       // x-projection chunk
    {
        const int lc = (c == 3) ? 8 : 14;
        const ULL* pf = (const ULL*)(Wf_w + j * 168 + 68 + kb);
        const ULL* ph = (const ULL*)(Wh_w + j * 168 + 68 + kb);
        #pragma unroll
        for (int t = 0; t < 14; t++) {
            wf2[t] = (t < lc) ? pf[t] : 0ull;
            wh2[t] = (t < lc) ? ph[t] : 0ull;
        }
        const ULL* px = (const ULL*)(Wf_w + j * 168 + xk);
        const ULL* qx = (const ULL*)(Wh_w + j * 168 + xk);
        #pragma unroll
        for (int t = 0; t < 8; t++) { wfx[t] = px[t]; whx[t] = qx[t]; }
    }
    // ctx-folded biases for row j
    float cb_f = Wf_b[j], cb_h = Wh_b[j];
    #pragma unroll
    for (int cc = 0; cc < 4; cc++) {
        float cv = ctx[cc];
        cb_f += cv * Wf_w[j * 168 + 64 + cc];
        cb_h += cv * Wh_w[j * 168 + 64 + cc];
    }

    // ---- init: h0 = 0 (incl. zero padding), x tile for s = 0 ---------------
    for (int idx = tid; idx < 4 * 112; idx += 400) {
        (&sh_h[0][0])[idx]  = 0.f;
        (&sh_fh[0][0])[idx] = 0.f;
    }
    if (tid < 256) {
        int r = tid >> 6, i = tid & 63;
        xs[0][r][i] = x[((size_t)(rbase + r) * 512) * 64 + i];
    }
    __syncthreads();

    const int r = c;  // batch row this thread owns in activation phases
    float fg = 0.f, hold = 0.f;

    #pragma unroll 1
    for (int s = 0; s < 512; s++) {
        const int buf = s & 1;

        // prefetch x tile for s+1 into buf^1. Safe: last reader of buf^1 was
        // step s-1's MV2, which finished before that step's closing barrier.
        if (tid < 256) {
            int rr = tid >> 6, i = tid & 63;
            int sp = (s < 511) ? s + 1 : 511;
            xs[buf ^ 1][rr][i] = x[((size_t)(rbase + rr) * 512 + sp) * 64 + i];
        }

        // ---- MV1: Wf_h . h + Wf_x . x (own chunks, 4 rows) -----------------
        {
            ULL a0 = 0ull, a1 = 0ull, a2 = 0ull, a3 = 0ull;
            #pragma unroll
            for (int t = 0; t < 7; t++) {
                ulonglong2 h0 = *(const ulonglong2*)&sh_h[0][kb + 4 * t];
                ulonglong2 h1 = *(const ulonglong2*)&sh_h[1][kb + 4 * t];
                ulonglong2 h2 = *(const ulonglong2*)&sh_h[2][kb + 4 * t];
                ulonglong2 h3 = *(const ulonglong2*)&sh_h[3][kb + 4 * t];
                a0 = fma2(wf2[2 * t], h0.x, a0); a0 = fma2(wf2[2 * t + 1], h0.y, a0);
                a1 = fma2(wf2[2 * t], h1.x, a1); a1 = fma2(wf2[2 * t + 1], h1.y, a1);
                a2 = fma2(wf2[2 * t], h2.x, a2); a2 = fma2(wf2[2 * t + 1], h2.y, a2);
                a3 = fma2(wf2[2 * t], h3.x, a3); a3 = fma2(wf2[2 * t + 1], h3.y, a3);
            }
            #pragma unroll
            for (int t = 0; t < 4; t++) {
                ulonglong2 x0 = *(const ulonglong2*)&xs[buf][0][xk + 4 * t];
                ulonglong2 x1 = *(const ulonglong2*)&xs[buf][1][xk + 4 * t];
                ulonglong2 x2 = *(const ulonglong2*)&xs[buf][2][xk + 4 * t];
                ulonglong2 x3 = *(const ulonglong2*)&xs[buf][3][xk + 4 * t];
                a0 = fma2(wfx[2 * t], x0.x, a0); a0 = fma2(wfx[2 * t + 1], x0.y, a0);
                a1 = fma2(wfx[2 * t], x1.x, a1); a1 = fma2(wfx[2 * t + 1], x1.y, a1);
                a2 = fma2(wfx[2 * t], x2.x, a2); a2 = fma2(wfx[2 * t + 1], x2.y, a2);
                a3 = fma2(wfx[2 * t], x3.x, a3); a3 = fma2(wfx[2 * t + 1], x3.y, a3);
            }
            *(float4*)&sh_p[c][j][0] =
                make_float4(hsum2(a0), hsum2(a1), hsum2(a2), hsum2(a3));
        }
        __syncthreads();  // (1)

        // ---- act 1: f-gate, f*h (scalar shared reads — no runtime-indexed
        //      register arrays; that spilled to local in R9/R10) -------------
        {
            float sum = sh_p[0][j][r] + sh_p[1][j][r] + sh_p[2][j][r] + sh_p[3][j][r];
            fg = sigmoidf_(sum + cb_f);
            hold = sh_h[r][j];
            sh_fh[r][j] = fg * hold;
        }
        __syncthreads();  // (2)

        // ---- MV2: Wh_h . (f*h) + Wh_x . x ----------------------------------
        {
            ULL a0 = 0ull, a1 = 0ull, a2 = 0ull, a3 = 0ull;
            #pragma unroll
            for (int t = 0; t < 7; t++) {
                ulonglong2 h0 = *(const ulonglong2*)&sh_fh[0][kb + 4 * t];
                ulonglong2 h1 = *(const ulonglong2*)&sh_fh[1][kb + 4 * t];
                ulonglong2 h2 = *(const ulonglong2*)&sh_fh[2][kb + 4 * t];
                ulonglong2 h3 = *(const ulonglong2*)&sh_fh[3][kb + 4 * t];
                a0 = fma2(wh2[2 * t], h0.x, a0); a0 = fma2(wh2[2 * t + 1], h0.y, a0);
                a1 = fma2(wh2[2 * t], h1.x, a1); a1 = fma2(wh2[2 * t + 1], h1.y, a1);
                a2 = fma2(wh2[2 * t], h2.x, a2); a2 = fma2(wh2[2 * t + 1], h2.y, a2);
                a3 = fma2(wh2[2 * t], h3.x, a3); a3 = fma2(wh2[2 * t + 1], h3.y, a3);
            }
            #pragma unroll
            for (int t = 0; t < 4; t++) {
                ulonglong2 x0 = *(const ulonglong2*)&xs[buf][0][xk + 4 * t];
                ulonglong2 x1 = *(const ulonglong2*)&xs[buf][1][xk + 4 * t];
                ulonglong2 x2 = *(const ulonglong2*)&xs[buf][2][xk + 4 * t];
                ulonglong2 x3 = *(const ulonglong2*)&xs[buf][3][xk + 4 * t];
                a0 = fma2(whx[2 * t], x0.x, a0); a0 = fma2(whx[2 * t + 1], x0.y, a0);
                a1 = fma2(whx[2 * t], x1.x, a1); a1 = fma2(whx[2 * t + 1], x1.y, a1);
                a2 = fma2(whx[2 * t], x2.x, a2); a2 = fma2(whx[2 * t + 1], x2.y, a2);
                a3 = fma2(whx[2 * t], x3.x, a3); a3 = fma2(whx[2 * t + 1], x3.y, a3);
            }
            *(float4*)&sh_p[c][j][0] =
                make_float4(hsum2(a0), hsum2(a1), hsum2(a2), hsum2(a3));
        }
        __syncthreads();  // (3)

        // ---- act 2: h update + store ---------------------------------------
        {
            float sum = sh_p[0][j][r] + sh_p[1][j][r] + sh_p[2][j][r] + sh_p[3][j][r];
            float ht = tanhf_(sum + cb_h);
            float hn = hold + fg * (ht - hold);
            sh_h[r][j] = hn;
            hidden[((size_t)(rbase + r) * 512 + s) * 100 + j] = hn;
        }
        __syncthreads();  // (4) sh_h visible; orders next prefetch vs MV2 reads
    }
}

// ---------------- output head (warp per output) ------------------------------
__global__ void head_kernel(const float* __restrict__ hidden,
                            const float* __restrict__ ro_w,
                            const float* __restrict__ ro_b,
                            float* __restrict__ out)
{
    int warp = (blockIdx.x * blockDim.x + threadIdx.x) >> 5;
    int lane = threadIdx.x & 31;
    if (warp >= 512 * 7) return;
    int b = warp / 7, o = warp - b * 7;
    const float* h = hidden + ((size_t)b * 512 + 511) * 100;
    const float* w = ro_w + o * 100;
    float acc = 0.f;
    for (int k = lane; k < 100; k += 32) acc += h[k] * w[k];
    #pragma unroll
    for (int d = 16; d; d >>= 1) acc += __shfl_xor_sync(0xFFFFFFFFu, acc, d);
    if (lane == 0) out[b * 7 + o] = acc + ro_b[o];
}

// ---------------- launch -----------------------------------------------------
extern "C" void kernel_launch(void* const* d_in, const int* in_sizes, int n_in,
                              void* d_out, int out_size)
{
    (void)in_sizes; (void)n_in; (void)out_size;
    const float* x     = (const float*)d_in[0];
    const float* ctx   = (const float*)d_in[1];
    const float* Wf_w  = (const float*)d_in[2];
    const float* Wf_b  = (const float*)d_in[3];
    const float* Wh_w  = (const float*)d_in[4];
    const float* Wh_b  = (const float*)d_in[5];
    const float* ro_w  = (const float*)d_in[6];
    const float* ro_b  = (const float*)d_in[7];

    float* out    = (float*)d_out;
    float* hidden = out + 512 * 7;

    scan_fused<<<128, 400>>>(x, ctx, Wf_w, Wf_b, Wh_w, Wh_b, hidden);
    head_kernel<<<448, 256>>>(hidden, ro_w, ro_b, out);
}

// round 15
// speedup vs baseline: 1.5012x; 1.1562x over previous
#include <cuda_runtime.h>
#include <cuda_bf16.h>

// Problem: B=512, S=512, I=64, C=4, H=100, O=7
// out = [output (512*7)] ++ [hidden_states (512*512*100)]

#define ULL unsigned long long

// ---------------- scratch (device globals; no runtime allocation) -----------
__device__ float g_xf[512 * 512 * 100];
__device__ float g_xh[512 * 512 * 100];

// ---------------- helpers ---------------------------------------------------
__device__ __forceinline__ ULL fma2(ULL a, ULL b, ULL c) {
    ULL d;
    asm("fma.rn.f32x2 %0, %1, %2, %3;" : "=l"(d) : "l"(a), "l"(b), "l"(c));
    return d;
}
__device__ __forceinline__ float hsum2(ULL a) {
    float lo, hi;
    asm("mov.b64 {%0,%1}, %2;" : "=f"(lo), "=f"(hi) : "l"(a));
    return lo + hi;
}
__device__ __forceinline__ void unpack2(ULL a, float& lo, float& hi) {
    asm("mov.b64 {%0,%1}, %2;" : "=f"(lo), "=f"(hi) : "l"(a));
}
__device__ __forceinline__ ULL dup2(float v) {
    ULL d;
    asm("mov.b64 %0, {%1,%1};" : "=l"(d) : "f"(v));
    return d;
}
__device__ __forceinline__ float sigmoidf_(float v) {
    return __fdividef(1.f, 1.f + __expf(-v));
}
__device__ __forceinline__ float tanhf_(float v) {
    return 1.f - __fdividef(2.f, __expf(2.f * v) + 1.f);
}

// ---------------- K1: pre-GEMM (R12 version: best measured, 244us) -----------
#define PRE_XSF   (64 * 128)
#define PRE_PITCH 68
#define PRE_UF    (128 * PRE_PITCH)
#define PRE_CBF   256
#define PRE_SMEM  ((PRE_XSF + PRE_UF + PRE_CBF) * 4)

__global__ void __launch_bounds__(256, 3)
pre_kernel(const float* __restrict__ x, const float* __restrict__ ctx,
           const float* __restrict__ Wf_w, const float* __restrict__ Wf_b,
           const float* __restrict__ Wh_w, const float* __restrict__ Wh_b)
{
    extern __shared__ float sm[];
    float* xs  = sm;                      // [64][128]  x transposed
    float* ws  = sm + PRE_XSF;            // [64][68]   w transposed  (union lo)
    float* sht = sm + PRE_XSF;            // [128][68]  store staging (union)
    float* cb  = sm + PRE_XSF + PRE_UF;   // [256]      ctx-folded bias

    const int tid = threadIdx.x;
    const int pg = tid & 31;
    const int jg = tid >> 5;
    const size_t pbase = (size_t)blockIdx.x * 128;

    {
        int r = tid;
        float v = 0.f;
        if (r < 200) {
            const float* W = (r < 100) ? (Wf_w + r * 168) : (Wh_w + (r - 100) * 168);
            v = (r < 100) ? Wf_b[r] : Wh_b[r - 100];
            #pragma unroll
            for (int c = 0; c < 4; c++) v += ctx[c] * W[64 + c];
        }
        cb[r] = v;
    }

    for (int idx = tid; idx < 2048; idx += 256) {
        int p = idx >> 4, k4 = (idx & 15) << 2;
        float4 v = *(const float4*)(x + (pbase + p) * 64 + k4);
        xs[(k4 + 0) * 128 + p] = v.x;
        xs[(k4 + 1) * 128 + p] = v.y;
        xs[(k4 + 2) * 128 + p] = v.z;
        xs[(k4 + 3) * 128 + p] = v.w;
    }
    __syncthreads();

    #pragma unroll 1
    for (int pass = 0; pass < 4; pass++) {
        for (int idx = tid; idx < 1024; idx += 256) {
            int row = idx >> 4, k4 = (idx & 15) << 2;
            int rg = pass * 64 + row;
            int rc = (rg < 200) ? rg : 199;
            const float* W = (rc < 100) ? (Wf_w + rc * 168) : (Wh_w + (rc - 100) * 168);
            float4 v = *(const float4*)(W + k4);
            ws[(k4 + 0) * 68 + row] = v.x;
            ws[(k4 + 1) * 68 + row] = v.y;
            ws[(k4 + 2) * 68 + row] = v.z;
            ws[(k4 + 3) * 68 + row] = v.w;
        }
        __syncthreads();

        ULL acc[4][4];
        #pragma unroll
        for (int a = 0; a < 4; a++)
            #pragma unroll
            for (int b = 0; b < 4; b++) acc[a][b] = 0ull;

        #pragma unroll 8
        for (int k = 0; k < 64; k++) {
            float4 xv = *(const float4*)(xs + k * 128 + pg * 4);
            ulonglong2 wa = *(const ulonglong2*)(ws + k * 68 + jg * 8);
            ulonglong2 wb = *(const ulonglong2*)(ws + k * 68 + jg * 8 + 4);
            ULL x0 = dup2(xv.x), x1 = dup2(xv.y), x2 = dup2(xv.z), x3 = dup2(xv.w);
            acc[0][0] = fma2(wa.x, x0, acc[0][0]);
            acc[0][1] = fma2(wa.x, x1, acc[0][1]);
            acc[0][2] = fma2(wa.x, x2, acc[0][2]);
            acc[0][3] = fma2(wa.x, x3, acc[0][3]);
            acc[1][0] = fma2(wa.y, x0, acc[1][0]);
            acc[1][1] = fma2(wa.y, x1, acc[1][1]);
            acc[1][2] = fma2(wa.y, x2, acc[1][2]);
            acc[1][3] = fma2(wa.y, x3, acc[1][3]);
            acc[2][0] = fma2(wb.x, x0, acc[2][0]);
            acc[2][1] = fma2(wb.x, x1, acc[2][1]);
            acc[2][2] = fma2(wb.x, x2, acc[2][2]);
            acc[2][3] = fma2(wb.x, x3, acc[2][3]);
            acc[3][0] = fma2(wb.y, x0, acc[3][0]);
            acc[3][1] = fma2(wb.y, x1, acc[3][1]);
            acc[3][2] = fma2(wb.y, x2, acc[3][2]);
            acc[3][3] = fma2(wb.y, x3, acc[3][3]);
        }
        __syncthreads();  // ws reads done before sht overwrites union

        const int rb = pass * 64 + jg * 8;
        float c0 = cb[rb + 0], c1 = cb[rb + 1], c2 = cb[rb + 2], c3 = cb[rb + 3];
        float c4 = cb[rb + 4], c5 = cb[rb + 5], c6 = cb[rb + 6], c7 = cb[rb + 7];
        #pragma unroll
        for (int i = 0; i < 4; i++) {
            int p = pg * 4 + i;
            float v0, v1, v2, v3, v4, v5, v6, v7;
            unpack2(acc[0][i], v0, v1);
            unpack2(acc[1][i], v2, v3);
            unpack2(acc[2][i], v4, v5);
            unpack2(acc[3][i], v6, v7);
            *(float4*)&sht[p * PRE_PITCH + jg * 8] =
                make_float4(v0 + c0, v1 + c1, v2 + c2, v3 + c3);
            *(float4*)&sht[p * PRE_PITCH + jg * 8 + 4] =
                make_float4(v4 + c4, v5 + c5, v6 + c6, v7 + c7);
        }
        __syncthreads();

        for (int f = tid; f < 2048; f += 256) {
            int pos = f >> 4, r4 = f & 15;
            int rg4 = pass * 64 + r4 * 4;
            float4 v = *(const float4*)&sht[pos * PRE_PITCH + r4 * 4];
            size_t po = (pbase + pos) * 100;
            if (rg4 < 100)       *(float4*)(g_xf + po + rg4)       = v;
            else if (rg4 < 200)  *(float4*)(g_xh + po + rg4 - 100) = v;
        }
        __syncthreads();
    }
}

// ---------------- K2: scan, 800 threads, 8 k-chunks --------------------------
// 128 blocks x 4 batch rows x 800 threads: thread (j = tid%100, c = tid/100).
// Chunk c covers k in [16c, 16c+16) (h rows padded to 128 with zeros;
// c=6: 2 real pairs, c=7: all zero — uniform control flow).
// Per-thread matvec work is HALF of the 400-thread version (16 LDS.128 +
// 32 fma2); 25 warps/SM cover LDS latency. Weight state only 16 ULL = 32
// regs, fitting the 80-reg cap at 800 threads.
// Partials: sh_p[chunk][j*5 + r] — pitch 5 (gcd(5,32)=1) makes the act-phase
// scalar reads conflict-free; epilogue writes 4 scalar STS (each stride-5,
// conflict-free).
__global__ void __launch_bounds__(800, 1)
scan_kernel(const float* __restrict__ Wf_w, const float* __restrict__ Wh_w,
            float* __restrict__ hidden)
{
    const int tid = threadIdx.x;
    const int c = tid / 100;          // 0..7
    const int j = tid - c * 100;
    const int kb = 16 * c;
    const int rbase = blockIdx.x * 4;

    __shared__ __align__(16) float sh_h[4][128];
    __shared__ __align__(16) float sh_fh[4][128];
    __shared__ __align__(16) float sh_p[8][500];   // [chunk][j*5 + r]

    // register-resident recurrence weights (k-pair packed), pad pairs = 0
    ULL wf2[8], wh2[8];
    {
        const int lc = (c < 6) ? 8 : ((c == 6) ? 2 : 0);  // real pairs (k<=99)
        const ULL* pf = (const ULL*)(Wf_w + j * 168 + 68 + kb);
        const ULL* ph = (const ULL*)(Wh_w + j * 168 + 68 + kb);
        #pragma unroll
        for (int t = 0; t < 8; t++) {
            wf2[t] = (t < lc) ? pf[t] : 0ull;
            wh2[t] = (t < lc) ? ph[t] : 0ull;
        }
    }

    // h0 = 0 (also zeroes k=100..127 padding)
    for (int idx = tid; idx < 4 * 128; idx += 800) {
        (&sh_h[0][0])[idx]  = 0.f;
        (&sh_fh[0][0])[idx] = 0.f;
    }
    __syncthreads();

    const int r = c;  // batch row owned in act phases (c<4 only)
    const bool actor = (c < 4);
    const size_t xbase = (size_t)(rbase + (actor ? r : 0)) * 51200 + j;
    float xf_cur = 0.f, xh_cur = 0.f;
    if (actor) { xf_cur = g_xf[xbase]; xh_cur = g_xh[xbase]; }
    float xf_nxt = 0.f, xh_nxt = 0.f, fg = 0.f, hold = 0.f;

    #pragma unroll 1
    for (int s = 0; s < 512; s++) {
        // -- matvec 1: Wf_h . h (own chunk, 4 rows)
        {
            ULL a0 = 0ull, a1 = 0ull, a2 = 0ull, a3 = 0ull;
            #pragma unroll
            for (int t = 0; t < 4; t++) {
                ulonglong2 h0 = *(const ulonglong2*)&sh_h[0][kb + 4 * t];
                ulonglong2 h1 = *(const ulonglong2*)&sh_h[1][kb + 4 * t];
                ulonglong2 h2 = *(const ulonglong2*)&sh_h[2][kb + 4 * t];
                ulonglong2 h3 = *(const ulonglong2*)&sh_h[3][kb + 4 * t];
                a0 = fma2(wf2[2 * t], h0.x, a0); a0 = fma2(wf2[2 * t + 1], h0.y, a0);
                a1 = fma2(wf2[2 * t], h1.x, a1); a1 = fma2(wf2[2 * t + 1], h1.y, a1);
                a2 = fma2(wf2[2 * t], h2.x, a2); a2 = fma2(wf2[2 * t + 1], h2.y, a2);
                a3 = fma2(wf2[2 * t], h3.x, a3); a3 = fma2(wf2[2 * t + 1], h3.y, a3);
            }
            float* p = &sh_p[c][j * 5];
            p[0] = hsum2(a0); p[1] = hsum2(a1); p[2] = hsum2(a2); p[3] = hsum2(a3);
        }
        __syncthreads();  // (1)

        // -- act 1: f-gate, f*h (c<4 threads; scalar shared reads)
        if (actor) {
            float sum = sh_p[0][j * 5 + r] + sh_p[1][j * 5 + r]
                      + sh_p[2][j * 5 + r] + sh_p[3][j * 5 + r]
                      + sh_p[4][j * 5 + r] + sh_p[5][j * 5 + r]
                      + sh_p[6][j * 5 + r] + sh_p[7][j * 5 + r];
            fg = sigmoidf_(sum + xf_cur);
            hold = sh_h[r][j];
            sh_fh[r][j] = fg * hold;
            int sp = (s < 511) ? s + 1 : 511;
            xf_nxt = g_xf[xbase + (size_t)sp * 100];
            xh_nxt = g_xh[xbase + (size_t)sp * 100];
        }
        __syncthreads();  // (2)

        // -- matvec 2: Wh_h . (f*h)
        {
            ULL a0 = 0ull, a1 = 0ull, a2 = 0ull, a3 = 0ull;
            #pragma unroll
            for (int t = 0; t < 4; t++) {
                ulonglong2 h0 = *(const ulonglong2*)&sh_fh[0][kb + 4 * t];
                ulonglong2 h1 = *(const ulonglong2*)&sh_fh[1][kb + 4 * t];
                ulonglong2 h2 = *(const ulonglong2*)&sh_fh[2][kb + 4 * t];
                ulonglong2 h3 = *(const ulonglong2*)&sh_fh[3][kb + 4 * t];
                a0 = fma2(wh2[2 * t], h0.x, a0); a0 = fma2(wh2[2 * t + 1], h0.y, a0);
                a1 = fma2(wh2[2 * t], h1.x, a1); a1 = fma2(wh2[2 * t + 1], h1.y, a1);
                a2 = fma2(wh2[2 * t], h2.x, a2); a2 = fma2(wh2[2 * t + 1], h2.y, a2);
                a3 = fma2(wh2[2 * t], h3.x, a3); a3 = fma2(wh2[2 * t + 1], h3.y, a3);
            }
            float* p = &sh_p[c][j * 5];
            p[0] = hsum2(a0); p[1] = hsum2(a1); p[2] = hsum2(a2); p[3] = hsum2(a3);
        }
        __syncthreads();  // (3)

        // -- act 2: h update + store
        if (actor) {
            float sum = sh_p[0][j * 5 + r] + sh_p[1][j * 5 + r]
                      + sh_p[2][j * 5 + r] + sh_p[3][j * 5 + r]
                      + sh_p[4][j * 5 + r] + sh_p[5][j * 5 + r]
                      + sh_p[6][j * 5 + r] + sh_p[7][j * 5 + r];
            float ht = tanhf_(sum + xh_cur);
            float hn = hold + fg * (ht - hold);
            sh_h[r][j] = hn;
            hidden[((size_t)(rbase + r) * 512 + s) * 100 + j] = hn;
            xf_cur = xf_nxt;
            xh_cur = xh_nxt;
        }
        __syncthreads();  // (4)
    }
}

// ---------------- K3: output head (warp per output) --------------------------
__global__ void head_kernel(const float* __restrict__ hidden,
                            const float* __restrict__ ro_w,
                            const float* __restrict__ ro_b,
                            float* __restrict__ out)
{
    int warp = (blockIdx.x * blockDim.x + threadIdx.x) >> 5;
    int lane = threadIdx.x & 31;
    if (warp >= 512 * 7) return;
    int b = warp / 7, o = warp - b * 7;
    const float* h = hidden + ((size_t)b * 512 + 511) * 100;
    const float* w = ro_w + o * 100;
    float acc = 0.f;
    for (int k = lane; k < 100; k += 32) acc += h[k] * w[k];
    #pragma unroll
    for (int d = 16; d; d >>= 1) acc += __shfl_xor_sync(0xFFFFFFFFu, acc, d);
    if (lane == 0) out[b * 7 + o] = acc + ro_b[o];
}

// ---------------- launch -----------------------------------------------------
extern "C" void kernel_launch(void* const* d_in, const int* in_sizes, int n_in,
                              void* d_out, int out_size)
{
    (void)in_sizes; (void)n_in; (void)out_size;
    const float* x     = (const float*)d_in[0];
    const float* ctx   = (const float*)d_in[1];
    const float* Wf_w  = (const float*)d_in[2];
    const float* Wf_b  = (const float*)d_in[3];
    const float* Wh_w  = (const float*)d_in[4];
    const float* Wh_b  = (const float*)d_in[5];
    const float* ro_w  = (const float*)d_in[6];
    const float* ro_b  = (const float*)d_in[7];

    float* out    = (float*)d_out;
    float* hidden = out + 512 * 7;

    cudaFuncSetAttribute(pre_kernel,
                         cudaFuncAttributeMaxDynamicSharedMemorySize, PRE_SMEM);
    pre_kernel<<<2048, 256, PRE_SMEM>>>(x, ctx, Wf_w, Wf_b, Wh_w, Wh_b);
    scan_kernel<<<128, 800>>>(Wf_w, Wh_w, hidden);
    head_kernel<<<448, 256>>>(hidden, ro_w, ro_b, out);
}

// round 16
// speedup vs baseline: 1.5382x; 1.0246x over previous
#include <cuda_runtime.h>
#include <cuda_bf16.h>

// Problem: B=512, S=512, I=64, C=4, H=100, O=7
// out = [output (512*7)] ++ [hidden_states (512*512*100)]

#define ULL unsigned long long

// ---------------- scratch (device globals; no runtime allocation) -----------
__device__ float g_xf[512 * 512 * 100];
__device__ float g_xh[512 * 512 * 100];

// ---------------- helpers ---------------------------------------------------
__device__ __forceinline__ ULL fma2(ULL a, ULL b, ULL c) {
    ULL d;
    asm("fma.rn.f32x2 %0, %1, %2, %3;" : "=l"(d) : "l"(a), "l"(b), "l"(c));
    return d;
}
__device__ __forceinline__ float hsum2(ULL a) {
    float lo, hi;
    asm("mov.b64 {%0,%1}, %2;" : "=f"(lo), "=f"(hi) : "l"(a));
    return lo + hi;
}
__device__ __forceinline__ void unpack2(ULL a, float& lo, float& hi) {
    asm("mov.b64 {%0,%1}, %2;" : "=f"(lo), "=f"(hi) : "l"(a));
}
__device__ __forceinline__ ULL dup2(float v) {
    ULL d;
    asm("mov.b64 %0, {%1,%1};" : "=l"(d) : "f"(v));
    return d;
}
__device__ __forceinline__ float sigmoidf_(float v) {
    return __fdividef(1.f, 1.f + __expf(-v));
}
__device__ __forceinline__ float tanhf_(float v) {
    return 1.f - __fdividef(2.f, __expf(2.f * v) + 1.f);
}

// ---------------- K1: pre-GEMM v6 --------------------------------------------
// 1024 blocks x 256 threads; tile 256 positions x 64 w-rows/pass, 4 passes
// over 200 stacked rows (0..99 = f-gate, 100..199 = h-gate).
// Thread (pg = tid&63, jg = tid>>6): frag = 16 rows (8 j-pair ULLs) x 4
// positions, positions STRIDED by 64 (pg, pg+64, pg+128, pg+192).
// Per thread-k: 32 fma2 vs 8 L1 wavefronts (4x LDS.32 x + 4x broadcast
// LDS.128 w) -> fma-bound (prior 4x4 frag was 16:6, LDS/fma dead-heat).
// xs pitch 257 kills the old 16-way transpose-STS conflict (stride 4*257
// == 4 mod 32). Staging: two 32-row halves, sht[256][36]; strided-pos
// mapping makes stage STS.128 (stride 36 == 4 mod 32) and readout
// (pos-major) conflict-free.
#define PRE_XP    257
#define PRE_XSF   (64 * PRE_XP)            // 16448 floats
#define PRE_SP    36
#define PRE_UF    (256 * PRE_SP)           // 9216 floats (>= ws 64*68=4352)
#define PRE_CBF   256
#define PRE_SMEM  ((PRE_XSF + PRE_UF + PRE_CBF) * 4)

__global__ void __launch_bounds__(256, 2)
pre_kernel(const float* __restrict__ x, const float* __restrict__ ctx,
           const float* __restrict__ Wf_w, const float* __restrict__ Wf_b,
           const float* __restrict__ Wh_w, const float* __restrict__ Wh_b)
{
    extern __shared__ float sm[];
    float* xs  = sm;                      // [64][257]  x transposed
    float* ws  = sm + PRE_XSF;            // [64][68]   w transposed (union lo)
    float* sht = sm + PRE_XSF;            // [256][36]  store staging (union)
    float* cb  = sm + PRE_XSF + PRE_UF;   // [256]      ctx-folded bias

    const int tid = threadIdx.x;
    const int pg = tid & 63;
    const int jg = tid >> 6;
    const size_t pbase = (size_t)blockIdx.x * 256;

    // ctx-folded bias for all 200 rows (pad rows -> 0)
    {
        int r = tid;
        float v = 0.f;
        if (r < 200) {
            const float* W = (r < 100) ? (Wf_w + r * 168) : (Wh_w + (r - 100) * 168);
            v = (r < 100) ? Wf_b[r] : Wh_b[r - 100];
            #pragma unroll
            for (int c = 0; c < 4; c++) v += ctx[c] * W[64 + c];
        }
        cb[r] = v;
    }

    // load x tile transposed: x[pbase+p][k] -> xs[k][p], pitch 257
    for (int idx = tid; idx < 4096; idx += 256) {
        int p = idx >> 4, k4 = (idx & 15) << 2;
        float4 v = *(const float4*)(x + (pbase + p) * 64 + k4);
        xs[(k4 + 0) * PRE_XP + p] = v.x;
        xs[(k4 + 1) * PRE_XP + p] = v.y;
        xs[(k4 + 2) * PRE_XP + p] = v.z;
        xs[(k4 + 3) * PRE_XP + p] = v.w;
    }
    __syncthreads();

    #pragma unroll 1
    for (int pass = 0; pass < 4; pass++) {
        // load this pass's 64 rows of weights transposed: W[row][k] -> ws[k][row]
        for (int idx = tid; idx < 1024; idx += 256) {
            int row = idx >> 4, k4 = (idx & 15) << 2;
            int rg = pass * 64 + row;
            int rc = (rg < 200) ? rg : 199;   // clamp (values discarded at store)
            const float* W = (rc < 100) ? (Wf_w + rc * 168) : (Wh_w + (rc - 100) * 168);
            float4 v = *(const float4*)(W + k4);
            ws[(k4 + 0) * 68 + row] = v.x;
            ws[(k4 + 1) * 68 + row] = v.y;
            ws[(k4 + 2) * 68 + row] = v.z;
            ws[(k4 + 3) * 68 + row] = v.w;
        }
        __syncthreads();

        ULL acc[8][4];  // [j-pair][pos]
        #pragma unroll
        for (int a = 0; a < 8; a++)
            #pragma unroll
            for (int b = 0; b < 4; b++) acc[a][b] = 0ull;

        #pragma unroll 4
        for (int k = 0; k < 64; k++) {
            float xv0 = xs[k * PRE_XP + pg];
            float xv1 = xs[k * PRE_XP + pg + 64];
            float xv2 = xs[k * PRE_XP + pg + 128];
            float xv3 = xs[k * PRE_XP + pg + 192];
            ulonglong2 wa = *(const ulonglong2*)(ws + k * 68 + jg * 16);
            ulonglong2 wb = *(const ulonglong2*)(ws + k * 68 + jg * 16 + 4);
            ulonglong2 wc = *(const ulonglong2*)(ws + k * 68 + jg * 16 + 8);
            ulonglong2 wd = *(const ulonglong2*)(ws + k * 68 + jg * 16 + 12);
            ULL d0 = dup2(xv0), d1 = dup2(xv1), d2 = dup2(xv2), d3 = dup2(xv3);
            acc[0][0] = fma2(wa.x, d0, acc[0][0]);
            acc[0][1] = fma2(wa.x, d1, acc[0][1]);
            acc[0][2] = fma2(wa.x, d2, acc[0][2]);
            acc[0][3] = fma2(wa.x, d3, acc[0][3]);
            acc[1][0] = fma2(wa.y, d0, acc[1][0]);
            acc[1][1] = fma2(wa.y, d1, acc[1][1]);
            acc[1][2] = fma2(wa.y, d2, acc[1][2]);
            acc[1][3] = fma2(wa.y, d3, acc[1][3]);
            acc[2][0] = fma2(wb.x, d0, acc[2][0]);
            acc[2][1] = fma2(wb.x, d1, acc[2][1]);
            acc[2][2] = fma2(wb.x, d2, acc[2][2]);
            acc[2][3] = fma2(wb.x, d3, acc[2][3]);
            acc[3][0] = fma2(wb.y, d0, acc[3][0]);
            acc[3][1] = fma2(wb.y, d1, acc[3][1]);
            acc[3][2] = fma2(wb.y, d2, acc[3][2]);
            acc[3][3] = fma2(wb.y, d3, acc[3][3]);
            acc[4][0] = fma2(wc.x, d0, acc[4][0]);
            acc[4][1] = fma2(wc.x, d1, acc[4][1]);
            acc[4][2] = fma2(wc.x, d2, acc[4][2]);
            acc[4][3] = fma2(wc.x, d3, acc[4][3]);
            acc[5][0] = fma2(wc.y, d0, acc[5][0]);
            acc[5][1] = fma2(wc.y, d1, acc[5][1]);
            acc[5][2] = fma2(wc.y, d2, acc[5][2]);
            acc[5][3] = fma2(wc.y, d3, acc[5][3]);
            acc[6][0] = fma2(wd.x, d0, acc[6][0]);
            acc[6][1] = fma2(wd.x, d1, acc[6][1]);
            acc[6][2] = fma2(wd.x, d2, acc[6][2]);
            acc[6][3] = fma2(wd.x, d3, acc[6][3]);
            acc[7][0] = fma2(wd.y, d0, acc[7][0]);
            acc[7][1] = fma2(wd.y, d1, acc[7][1]);
            acc[7][2] = fma2(wd.y, d2, acc[7][2]);
            acc[7][3] = fma2(wd.y, d3, acc[7][3]);
        }
        __syncthreads();  // all ws reads done before sht overwrites the union

        // ---- epilogue: two 32-row halves -----------------------------------
        const int rb = pass * 64 + jg * 16;   // this thread's first row
        #pragma unroll 1
        for (int half = 0; half < 2; half++) {
            if ((jg >> 1) == half) {
                const int colbase = (jg & 1) * 16;
                #pragma unroll
                for (int i = 0; i < 4; i++) {
                    int p = pg + 64 * i;      // strided positions
                    #pragma unroll
                    for (int q = 0; q < 4; q++) {
                        float lo0, hi0, lo1, hi1;
                        unpack2(acc[2 * q][i],     lo0, hi0);
                        unpack2(acc[2 * q + 1][i], lo1, hi1);
                        float b0 = cb[rb + 4 * q + 0];
                        float b1 = cb[rb + 4 * q + 1];
                        float b2 = cb[rb + 4 * q + 2];
                        float b3 = cb[rb + 4 * q + 3];
                        *(float4*)&sht[p * PRE_SP + colbase + 4 * q] =
                            make_float4(lo0 + b0, hi0 + b1, lo1 + b2, hi1 + b3);
                    }
                }
            }
            __syncthreads();

            // coalesced store of 32 consecutive rows (128B runs per pos)
            for (int f = tid; f < 2048; f += 256) {
                int pos = f >> 3, r4 = f & 7;
                int rg4 = pass * 64 + half * 32 + r4 * 4;  // mult of 4
                float4 v = *(const float4*)&sht[pos * PRE_SP + r4 * 4];
                size_t po = (pbase + pos) * 100;
                if (rg4 < 100)       *(float4*)(g_xf + po + rg4)       = v;
                else if (rg4 < 200)  *(float4*)(g_xh + po + rg4 - 100) = v;
            }
            __syncthreads();  // sht reused (next half / next pass's ws)
        }
    }
}

// ---------------- K2: sequential scan (R4 structure, best measured ~670us) ---
// 128 blocks x 4 batch rows x 400 threads: thread (j = tid%100, c = tid/100).
// Matvecs: chunk c covers k in [28c, 28c+28) (padded to 112 with zeros).
// Activation/update: thread (j,c) owns row r=c; partials read as scalar
// dynamic-index SHARED loads (runtime-indexed register arrays spill).
__global__ void __launch_bounds__(400, 1)
scan_kernel(const float* __restrict__ Wf_w, const float* __restrict__ Wh_w,
            float* __restrict__ hidden)
{
    const int tid = threadIdx.x;
    const int c = tid / 100;
    const int j = tid - c * 100;
    const int kb = 28 * c;
    const int rbase = blockIdx.x * 4;

    __shared__ __align__(16) float sh_h[4][112];
    __shared__ __align__(16) float sh_fh[4][112];
    __shared__ __align__(16) float sh_p[4][100][4];  // [chunk][j][row]

    ULL wf2[14], wh2[14];
    {
        const int lc = (c == 3) ? 8 : 14;
        const ULL* pf = (const ULL*)(Wf_w + j * 168 + 68 + kb);
        const ULL* ph = (const ULL*)(Wh_w + j * 168 + 68 + kb);
        #pragma unroll
        for (int t = 0; t < 14; t++) {
            wf2[t] = (t < lc) ? pf[t] : 0ull;
            wh2[t] = (t < lc) ? ph[t] : 0ull;
        }
    }

    for (int idx = tid; idx < 4 * 112; idx += 400) {
        (&sh_h[0][0])[idx]  = 0.f;
        (&sh_fh[0][0])[idx] = 0.f;
    }
    __syncthreads();

    const int r = c;
    const size_t xbase = (size_t)(rbase + r) * 51200 + j;
    float xf_cur = g_xf[xbase];
    float xh_cur = g_xh[xbase];
    float xf_nxt = 0.f, xh_nxt = 0.f, fg = 0.f, hold = 0.f;

    #pragma unroll 1
    for (int s = 0; s < 512; s++) {
        // -- matvec 1: Wf_h . h
        {
            ULL a0 = 0ull, a1 = 0ull, a2 = 0ull, a3 = 0ull;
            #pragma unroll
            for (int t = 0; t < 7; t++) {
                ulonglong2 h0 = *(const ulonglong2*)&sh_h[0][kb + 4 * t];
                ulonglong2 h1 = *(const ulonglong2*)&sh_h[1][kb + 4 * t];
                ulonglong2 h2 = *(const ulonglong2*)&sh_h[2][kb + 4 * t];
                ulonglong2 h3 = *(const ulonglong2*)&sh_h[3][kb + 4 * t];
                a0 = fma2(wf2[2 * t], h0.x, a0); a0 = fma2(wf2[2 * t + 1], h0.y, a0);
                a1 = fma2(wf2[2 * t], h1.x, a1); a1 = fma2(wf2[2 * t + 1], h1.y, a1);
                a2 = fma2(wf2[2 * t], h2.x, a2); a2 = fma2(wf2[2 * t + 1], h2.y, a2);
                a3 = fma2(wf2[2 * t], h3.x, a3); a3 = fma2(wf2[2 * t + 1], h3.y, a3);
            }
            *(float4*)&sh_p[c][j][0] =
                make_float4(hsum2(a0), hsum2(a1), hsum2(a2), hsum2(a3));
        }
        __syncthreads();  // (1)

        // -- act 1: f-gate, f*h
        {
            float sum = sh_p[0][j][r] + sh_p[1][j][r] + sh_p[2][j][r] + sh_p[3][j][r];
            fg = sigmoidf_(sum + xf_cur);
            hold = sh_h[r][j];
            sh_fh[r][j] = fg * hold;
            int sp = (s < 511) ? s + 1 : 511;
            xf_nxt = g_xf[xbase + (size_t)sp * 100];
            xh_nxt = g_xh[xbase + (size_t)sp * 100];
        }
        __syncthreads();  // (2)

        // -- matvec 2: Wh_h . (f*h)
        {
            ULL a0 = 0ull, a1 = 0ull, a2 = 0ull, a3 = 0ull;
            #pragma unroll
            for (int t = 0; t < 7; t++) {
                ulonglong2 h0 = *(const ulonglong2*)&sh_fh[0][kb + 4 * t];
                ulonglong2 h1 = *(const ulonglong2*)&sh_fh[1][kb + 4 * t];
                ulonglong2 h2 = *(const ulonglong2*)&sh_fh[2][kb + 4 * t];
                ulonglong2 h3 = *(const ulonglong2*)&sh_fh[3][kb + 4 * t];
                a0 = fma2(wh2[2 * t], h0.x, a0); a0 = fma2(wh2[2 * t + 1], h0.y, a0);
                a1 = fma2(wh2[2 * t], h1.x, a1); a1 = fma2(wh2[2 * t + 1], h1.y, a1);
                a2 = fma2(wh2[2 * t], h2.x, a2); a2 = fma2(wh2[2 * t + 1], h2.y, a2);
                a3 = fma2(wh2[2 * t], h3.x, a3); a3 = fma2(wh2[2 * t + 1], h3.y, a3);
            }
            *(float4*)&sh_p[c][j][0] =
                make_float4(hsum2(a0), hsum2(a1), hsum2(a2), hsum2(a3));
        }
        __syncthreads();  // (3)

        // -- act 2: h update + store
        {
            float sum = sh_p[0][j][r] + sh_p[1][j][r] + sh_p[2][j][r] + sh_p[3][j][r];
            float ht = tanhf_(sum + xh_cur);
            float hn = hold + fg * (ht - hold);
            sh_h[r][j] = hn;
            hidden[((size_t)(rbase + r) * 512 + s) * 100 + j] = hn;
            xf_cur = xf_nxt;
            xh_cur = xh_nxt;
        }
        __syncthreads();  // (4)
    }
}

// ---------------- K3: output head (warp per output) --------------------------
__global__ void head_kernel(const float* __restrict__ hidden,
                            const float* __restrict__ ro_w,
                            const float* __restrict__ ro_b,
                            float* __restrict__ out)
{
    int warp = (blockIdx.x * blockDim.x + threadIdx.x) >> 5;
    int lane = threadIdx.x & 31;
    if (warp >= 512 * 7) return;
    int b = warp / 7, o = warp - b * 7;
    const float* h = hidden + ((size_t)b * 512 + 511) * 100;
    const float* w = ro_w + o * 100;
    float acc = 0.f;
    for (int k = lane; k < 100; k += 32) acc += h[k] * w[k];
    #pragma unroll
    for (int d = 16; d; d >>= 1) acc += __shfl_xor_sync(0xFFFFFFFFu, acc, d);
    if (lane == 0) out[b * 7 + o] = acc + ro_b[o];
}

// ---------------- launch -----------------------------------------------------
extern "C" void kernel_launch(void* const* d_in, const int* in_sizes, int n_in,
                              void* d_out, int out_size)
{
    (void)in_sizes; (void)n_in; (void)out_size;
    const float* x     = (const float*)d_in[0];
    const float* ctx   = (const float*)d_in[1];
    const float* Wf_w  = (const float*)d_in[2];
    const float* Wf_b  = (const float*)d_in[3];
    const float* Wh_w  = (const float*)d_in[4];
    const float* Wh_b  = (const float*)d_in[5];
    const float* ro_w  = (const float*)d_in[6];
    const float* ro_b  = (const float*)d_in[7];

    float* out    = (float*)d_out;
    float* hidden = out + 512 * 7;

    cudaFuncSetAttribute(pre_kernel,
                         cudaFuncAttributeMaxDynamicSharedMemorySize, PRE_SMEM);
    pre_kernel<<<1024, 256, PRE_SMEM>>>(x, ctx, Wf_w, Wf_b, Wh_w, Wh_b);
    scan_kernel<<<128, 400>>>(Wf_w, Wh_w, hidden);
    head_kernel<<<448, 256>>>(hidden, ro_w, ro_b, out);
}